// round 9
// baseline (speedup 1.0000x reference)
#include <cuda_runtime.h>
#include <cuda_fp16.h>
#include <math.h>
#include <stdint.h>

#define N_LEVELS 16
#define HASH_MASK 32767u
#define HASHMAP_SIZE 32768
#define PTS_PER_CTA 54272      // 37 ranges * 16 levels = 592 CTAs = 4 full waves
#define CTA_THREADS 1024
#define MAX_POINTS 2000000

#define TP_THREADS 1024
#define TP_PTS 1024
#define TP_STRIDE 17           // half2 units; odd -> conflict-free STS

struct ResArr { int r[N_LEVELS]; };

// level-major half2 scratch (carrying the 2^14 prescale): 128 MB, 256B-aligned for discard
__device__ __align__(256) __half2 g_scr[(size_t)MAX_POINTS * N_LEVELS];
// packed normalized coords: [x,y,z,t] per point, 32 MB
__device__ float4 g_pts[MAX_POINTS];

// Pack + normalize, 4 points per thread, fully vectorized.
__global__ void __launch_bounds__(512)
prep_kernel(const float* __restrict__ coords,
            const float* __restrict__ ts, int n)
{
    int i = blockIdx.x * blockDim.x + threadIdx.x;   // quad index
    int nq = n >> 2;
    if (i < nq) {
        const float4* __restrict__ c4 = (const float4*)coords;
        float4 a = c4[3 * i + 0];   // x0 y0 z0 x1
        float4 b = c4[3 * i + 1];   // y1 z1 x2 y2
        float4 c = c4[3 * i + 2];   // z2 x3 y3 z3
        float4 t4 = ((const float4*)ts)[i];
        float t0 = fminf(fmaxf(t4.x, 0.0f), 1.0f);
        float t1 = fminf(fmaxf(t4.y, 0.0f), 1.0f);
        float t2 = fminf(fmaxf(t4.z, 0.0f), 1.0f);
        float t3 = fminf(fmaxf(t4.w, 0.0f), 1.0f);
        g_pts[4 * i + 0] = make_float4((a.x + 50.0f) / 100.0f, (a.y + 50.0f) / 100.0f,
                                       (a.z + 50.0f) / 100.0f, t0);
        g_pts[4 * i + 1] = make_float4((a.w + 50.0f) / 100.0f, (b.x + 50.0f) / 100.0f,
                                       (b.y + 50.0f) / 100.0f, t1);
        g_pts[4 * i + 2] = make_float4((b.z + 50.0f) / 100.0f, (b.w + 50.0f) / 100.0f,
                                       (c.x + 50.0f) / 100.0f, t2);
        g_pts[4 * i + 3] = make_float4((c.y + 50.0f) / 100.0f, (c.z + 50.0f) / 100.0f,
                                       (c.w + 50.0f) / 100.0f, t3);
    }
    // scalar tail (n not multiple of 4)
    int tail0 = nq << 2;
    int p = tail0 + i;
    if (i < (n - tail0)) {
        float x = (coords[3 * p + 0] + 50.0f) / 100.0f;
        float y = (coords[3 * p + 1] + 50.0f) / 100.0f;
        float z = (coords[3 * p + 2] + 50.0f) / 100.0f;
        float t = fminf(fmaxf(ts[p], 0.0f), 1.0f);
        g_pts[p] = make_float4(x, y, z, t);
    }
}

__global__ void __launch_bounds__(CTA_THREADS)
hash_enc4d_smem_kernel(const float* __restrict__ tables,
                       ResArr res, int n)
{
    extern __shared__ __half2 s_tbl[];  // 32768 entries = 128 KB

    const int l = blockIdx.x;  // level fastest-varying: co-resident levels share coords in L2

    // Load fp32 table slice, convert inline to prescaled half2.
    {
        const float4* __restrict__ src = (const float4*)(tables + (size_t)l * HASHMAP_SIZE * 2);
#pragma unroll
        for (int i = threadIdx.x; i < HASHMAP_SIZE / 2; i += CTA_THREADS) {
            float4 v = src[i];
            s_tbl[2 * i + 0] = __floats2half2_rn(v.x * 16384.0f, v.y * 16384.0f);
            s_tbl[2 * i + 1] = __floats2half2_rn(v.z * 16384.0f, v.w * 16384.0f);
        }
    }
    __syncthreads();

    const float rf = (float)res.r[l];
    const uint32_t P1 = 2654435761u, P2 = 805459861u, P3 = 3674653429u;
    __half2* __restrict__ sc = g_scr + (size_t)l * n;

    const int base = blockIdx.y * PTS_PER_CTA;
    const int end = min(base + PTS_PER_CTA, n);

    for (int p = base + threadIdx.x; p < end; p += CTA_THREADS) {
        float4 c = g_pts[p];                    // single LDG.128
        float sx = c.x * rf, sy = c.y * rf, sz = c.z * rf, st = c.w * rf;

        float gxf = floorf(sx), gyf = floorf(sy), gzf = floorf(sz), gtf = floorf(st);
        float fx = sx - gxf, fy = sy - gyf, fz = sz - gzf, ft = st - gtf;

        uint32_t gx = (uint32_t)(int)gxf;
        uint32_t gy = (uint32_t)(int)gyf;
        uint32_t gz = (uint32_t)(int)gzf;
        uint32_t gt = (uint32_t)(int)gtf;

        uint32_t tx0 = gx,      tx1 = gx + 1u;
        uint32_t ty0 = gy * P1, ty1 = ty0 + P1;
        uint32_t tz0 = gz * P2, tz1 = tz0 + P2;
        uint32_t tt0 = gt * P3, tt1 = tt0 + P3;

        uint32_t hxy[4], hzt[4];
        hxy[0] = tx0 ^ ty0; hxy[1] = tx1 ^ ty0;
        hxy[2] = tx0 ^ ty1; hxy[3] = tx1 ^ ty1;
        hzt[0] = tz0 ^ tt0; hzt[1] = tz1 ^ tt0;
        hzt[2] = tz0 ^ tt1; hzt[3] = tz1 ^ tt1;

        float ux = 1.0f - fx, uy = 1.0f - fy, uz = 1.0f - fz, ut = 1.0f - ft;
        float wxy[4], wzt[4];
        wxy[0] = ux * uy; wxy[1] = fx * uy; wxy[2] = ux * fy; wxy[3] = fx * fy;
        wzt[0] = uz * ut; wzt[1] = fz * ut; wzt[2] = uz * ft; wzt[3] = fz * ft;

        float a0 = 0.0f, a1 = 0.0f;
#pragma unroll
        for (int j = 0; j < 4; ++j) {
#pragma unroll
            for (int i = 0; i < 4; ++i) {
                uint32_t idx = (hxy[i] ^ hzt[j]) & HASH_MASK;
                float2 f = __half22float2(s_tbl[idx]);
                float w = wxy[i] * wzt[j];
                a0 = fmaf(w, f.x, a0);
                a1 = fmaf(w, f.y, a1);
            }
        }
        sc[p] = __floats2half2_rn(a0, a1);
    }
}

// Transpose + descale: g_scr[l][p] (half2, prescaled) -> out[p][...] (fp32).
__global__ void __launch_bounds__(TP_THREADS)
transpose_kernel(float* __restrict__ out, int n)
{
    extern __shared__ __half2 tile[];  // 1024*17*4 = 69632 B

    const int base = blockIdx.x * TP_PTS;
    float4* __restrict__ out4 = (float4*)out;

    if (base + TP_PTS <= n) {
#pragma unroll
        for (int l = 0; l < N_LEVELS; ++l) {
            const __half2* __restrict__ sc = g_scr + (size_t)l * n + base;
            tile[threadIdx.x * TP_STRIDE + l] = __ldcs(&sc[threadIdx.x]);
        }
        __syncthreads();

        // Discard consumed scratch lines (dirty, never read again) to kill writeback.
        // 16 levels x 4096 B = 512 lines of 128 B; threads 0..511 take one each.
        if (threadIdx.x < 512) {
            int l    = threadIdx.x >> 5;
            int line = threadIdx.x & 31;
            const char* ptr = (const char*)(g_scr + (size_t)l * n + base) + line * 128;
            asm volatile("discard.global.L2 [%0], 128;" :: "l"(ptr) : "memory");
        }

#pragma unroll
        for (int k = 0; k < 8; ++k) {
            int idx = threadIdx.x + k * TP_THREADS;
            int pt = idx >> 3;
            int q  = idx & 7;
            float2 f0 = __half22float2(tile[pt * TP_STRIDE + 2 * q]);
            float2 f1 = __half22float2(tile[pt * TP_STRIDE + 2 * q + 1]);
            __stcs(&out4[(size_t)(base + pt) * 8 + q],
                   make_float4(f0.x * 0x1p-14f, f0.y * 0x1p-14f,
                               f1.x * 0x1p-14f, f1.y * 0x1p-14f));
        }
    } else {
#pragma unroll
        for (int l = 0; l < N_LEVELS; ++l) {
            const __half2* __restrict__ sc = g_scr + (size_t)l * n;
            int p = base + threadIdx.x;
            tile[threadIdx.x * TP_STRIDE + l] =
                (p < n) ? __ldcs(&sc[p]) : __half2half2(__float2half(0.0f));
        }
        __syncthreads();

        for (int k = 0; k < 8; ++k) {
            int idx = threadIdx.x + k * TP_THREADS;
            int pt = idx >> 3;
            int q  = idx & 7;
            int p  = base + pt;
            if (p < n) {
                float2 f0 = __half22float2(tile[pt * TP_STRIDE + 2 * q]);
                float2 f1 = __half22float2(tile[pt * TP_STRIDE + 2 * q + 1]);
                __stcs(&out4[(size_t)p * 8 + q],
                       make_float4(f0.x * 0x1p-14f, f0.y * 0x1p-14f,
                                   f1.x * 0x1p-14f, f1.y * 0x1p-14f));
            }
        }
    }
}

extern "C" void kernel_launch(void* const* d_in, const int* in_sizes, int n_in,
                              void* d_out, int out_size)
{
    const float* coords = (const float*)d_in[0];
    const float* ts     = (const float*)d_in[1];
    const float* tables = (const float*)d_in[2];
    float* out          = (float*)d_out;

    int n = in_sizes[0] / 3;

    ResArr ra;
    for (int l = 0; l < N_LEVELS; ++l) {
        double f = (double)l / 15.0;
        double v = exp(log(16.0) * (1.0 - f) + log(512.0) * f);
        ra.r[l] = (int)v;
    }

    const int smem_main = HASHMAP_SIZE * (int)sizeof(__half2);        // 131072
    const int smem_tp   = TP_PTS * TP_STRIDE * (int)sizeof(__half2);  // 69632
    static int configured = 0;
    if (!configured) {
        cudaFuncSetAttribute(hash_enc4d_smem_kernel,
                             cudaFuncAttributeMaxDynamicSharedMemorySize, smem_main);
        cudaFuncSetAttribute(transpose_kernel,
                             cudaFuncAttributeMaxDynamicSharedMemorySize, smem_tp);
        configured = 1;
    }

    // 0) pack + normalize coords once -> float4 (vectorized, 4 pts/thread)
    {
        int nq = n >> 2;
        int blocks = (max(nq, n - (nq << 2)) + 511) / 512;
        if (blocks == 0) blocks = 1;
        prep_kernel<<<blocks, 512>>>(coords, ts, n);
    }

    // 1) 4-wave level-fastest encode -> half2 level-major scratch
    dim3 grid(N_LEVELS, (n + PTS_PER_CTA - 1) / PTS_PER_CTA);
    hash_enc4d_smem_kernel<<<grid, CTA_THREADS, smem_main>>>(tables, ra, n);

    // 2) streaming transpose + descale (+ L2 discard of consumed scratch)
    int tp_blocks = (n + TP_PTS - 1) / TP_PTS;
    transpose_kernel<<<tp_blocks, TP_THREADS, smem_tp>>>(out, n);
}

// round 11
// speedup vs baseline: 1.0245x; 1.0245x over previous
#include <cuda_runtime.h>
#include <cuda_fp16.h>
#include <math.h>
#include <stdint.h>

#define N_LEVELS 16
#define HASH_MASK 32767u
#define HASHMAP_SIZE 32768
#define PTS_PER_CTA 54272      // multiple of 4096; 37 ranges * 16 levels = 592 CTAs = 4 waves
#define CTA_THREADS 1024
#define MAX_POINTS 2000000

#define TP_THREADS 1024
#define TP_PTS 1024
#define TP_STRIDE 17           // half2 units; odd -> conflict-free STS

struct ResArr { int r[N_LEVELS]; };

// level-major half2 scratch (carrying the 2^14 prescale): 128 MB
__device__ __align__(256) __half2 g_scr[(size_t)MAX_POINTS * N_LEVELS];

__device__ __forceinline__ __half2 enc_point(float x, float y, float z, float t,
                                             float rf, const __half2* __restrict__ s_tbl)
{
    const uint32_t P1 = 2654435761u, P2 = 805459861u, P3 = 3674653429u;

    float sx = x * rf, sy = y * rf, sz = z * rf, st = t * rf;
    float gxf = floorf(sx), gyf = floorf(sy), gzf = floorf(sz), gtf = floorf(st);
    float fx = sx - gxf, fy = sy - gyf, fz = sz - gzf, ft = st - gtf;

    uint32_t gx = (uint32_t)(int)gxf;
    uint32_t gy = (uint32_t)(int)gyf;
    uint32_t gz = (uint32_t)(int)gzf;
    uint32_t gt = (uint32_t)(int)gtf;

    uint32_t tx0 = gx,      tx1 = gx + 1u;
    uint32_t ty0 = gy * P1, ty1 = ty0 + P1;
    uint32_t tz0 = gz * P2, tz1 = tz0 + P2;
    uint32_t tt0 = gt * P3, tt1 = tt0 + P3;

    uint32_t hxy[4], hzt[4];
    hxy[0] = tx0 ^ ty0; hxy[1] = tx1 ^ ty0;
    hxy[2] = tx0 ^ ty1; hxy[3] = tx1 ^ ty1;
    hzt[0] = tz0 ^ tt0; hzt[1] = tz1 ^ tt0;
    hzt[2] = tz0 ^ tt1; hzt[3] = tz1 ^ tt1;

    float ux = 1.0f - fx, uy = 1.0f - fy, uz = 1.0f - fz, ut = 1.0f - ft;
    float wxy[4], wzt[4];
    wxy[0] = ux * uy; wxy[1] = fx * uy; wxy[2] = ux * fy; wxy[3] = fx * fy;
    wzt[0] = uz * ut; wzt[1] = fz * ut; wzt[2] = uz * ft; wzt[3] = fz * ft;

    float a0 = 0.0f, a1 = 0.0f;
#pragma unroll
    for (int j = 0; j < 4; ++j) {
#pragma unroll
        for (int i = 0; i < 4; ++i) {
            uint32_t idx = (hxy[i] ^ hzt[j]) & HASH_MASK;
            float2 f = __half22float2(s_tbl[idx]);
            float w = wxy[i] * wzt[j];
            a0 = fmaf(w, f.x, a0);
            a1 = fmaf(w, f.y, a1);
        }
    }
    return __floats2half2_rn(a0, a1);
}

__global__ void __launch_bounds__(CTA_THREADS)
hash_enc4d_smem_kernel(const float* __restrict__ coords,
                       const float* __restrict__ ts,
                       const float* __restrict__ tables,
                       ResArr res, int n)
{
    extern __shared__ __half2 s_tbl[];  // 32768 entries = 128 KB

    const int l = blockIdx.x;  // level fastest-varying: co-resident levels share coords in L2

    // Load fp32 table slice, convert inline to prescaled half2.
    {
        const float4* __restrict__ src = (const float4*)(tables + (size_t)l * HASHMAP_SIZE * 2);
#pragma unroll
        for (int i = threadIdx.x; i < HASHMAP_SIZE / 2; i += CTA_THREADS) {
            float4 v = src[i];
            s_tbl[2 * i + 0] = __floats2half2_rn(v.x * 16384.0f, v.y * 16384.0f);
            s_tbl[2 * i + 1] = __floats2half2_rn(v.z * 16384.0f, v.w * 16384.0f);
        }
    }
    __syncthreads();

    const float rf = (float)res.r[l];
    __half2* __restrict__ sc = g_scr + (size_t)l * n;

    const int base = blockIdx.y * PTS_PER_CTA;
    const int nq_end = min(base + PTS_PER_CTA, n & ~3);  // quad-aligned region

    const float4* __restrict__ c4 = (const float4*)coords;
    const float4* __restrict__ t4 = (const float4*)ts;

    // ---- quad path: 4 consecutive points per thread, fully vectorized I/O ----
    for (int p = base + threadIdx.x * 4; p < nq_end; p += CTA_THREADS * 4) {
        int q = p >> 2;
        float4 a = c4[3 * q + 0];   // x0 y0 z0 x1
        float4 b = c4[3 * q + 1];   // y1 z1 x2 y2
        float4 c = c4[3 * q + 2];   // z2 x3 y3 z3
        float4 tt = t4[q];

        float xs[4] = {(a.x + 50.0f) / 100.0f, (a.w + 50.0f) / 100.0f,
                       (b.z + 50.0f) / 100.0f, (c.y + 50.0f) / 100.0f};
        float ys[4] = {(a.y + 50.0f) / 100.0f, (b.x + 50.0f) / 100.0f,
                       (b.w + 50.0f) / 100.0f, (c.z + 50.0f) / 100.0f};
        float zs[4] = {(a.z + 50.0f) / 100.0f, (b.y + 50.0f) / 100.0f,
                       (c.x + 50.0f) / 100.0f, (c.w + 50.0f) / 100.0f};
        float tc[4] = {fminf(fmaxf(tt.x, 0.0f), 1.0f), fminf(fmaxf(tt.y, 0.0f), 1.0f),
                       fminf(fmaxf(tt.z, 0.0f), 1.0f), fminf(fmaxf(tt.w, 0.0f), 1.0f)};

        union { __half2 h[4]; uint4 u; } r;
#pragma unroll
        for (int k = 0; k < 4; ++k)
            r.h[k] = enc_point(xs[k], ys[k], zs[k], tc[k], rf, s_tbl);

        // one 16-B coalesced store for 4 points
        *(uint4*)(sc + p) = r.u;
    }

    // ---- scalar tail (last CTA only, n % 4 points) ----
    if (base + PTS_PER_CTA >= n) {
        for (int p = (n & ~3) + threadIdx.x; p < n; p += CTA_THREADS) {
            float x = (coords[3 * p + 0] + 50.0f) / 100.0f;
            float y = (coords[3 * p + 1] + 50.0f) / 100.0f;
            float z = (coords[3 * p + 2] + 50.0f) / 100.0f;
            float t = fminf(fmaxf(ts[p], 0.0f), 1.0f);
            sc[p] = enc_point(x, y, z, t, rf, s_tbl);
        }
    }
}

// Transpose + descale: g_scr[l][p] (half2, prescaled) -> out[p][...] (fp32).
__global__ void __launch_bounds__(TP_THREADS)
transpose_kernel(float* __restrict__ out, int n)
{
    extern __shared__ __half2 tile[];  // 1024*17*4 = 69632 B

    const int base = blockIdx.x * TP_PTS;
    float4* __restrict__ out4 = (float4*)out;

    if (base + TP_PTS <= n) {
#pragma unroll
        for (int l = 0; l < N_LEVELS; ++l) {
            const __half2* __restrict__ sc = g_scr + (size_t)l * n + base;
            tile[threadIdx.x * TP_STRIDE + l] = sc[threadIdx.x];
        }
        __syncthreads();

#pragma unroll
        for (int k = 0; k < 8; ++k) {
            int idx = threadIdx.x + k * TP_THREADS;
            int pt = idx >> 3;
            int q  = idx & 7;
            float2 f0 = __half22float2(tile[pt * TP_STRIDE + 2 * q]);
            float2 f1 = __half22float2(tile[pt * TP_STRIDE + 2 * q + 1]);
            out4[(size_t)(base + pt) * 8 + q] =
                make_float4(f0.x * 0x1p-14f, f0.y * 0x1p-14f,
                            f1.x * 0x1p-14f, f1.y * 0x1p-14f);
        }
    } else {
#pragma unroll
        for (int l = 0; l < N_LEVELS; ++l) {
            const __half2* __restrict__ sc = g_scr + (size_t)l * n;
            int p = base + threadIdx.x;
            tile[threadIdx.x * TP_STRIDE + l] =
                (p < n) ? sc[p] : __half2half2(__float2half(0.0f));
        }
        __syncthreads();

        for (int k = 0; k < 8; ++k) {
            int idx = threadIdx.x + k * TP_THREADS;
            int pt = idx >> 3;
            int q  = idx & 7;
            int p  = base + pt;
            if (p < n) {
                float2 f0 = __half22float2(tile[pt * TP_STRIDE + 2 * q]);
                float2 f1 = __half22float2(tile[pt * TP_STRIDE + 2 * q + 1]);
                out4[(size_t)p * 8 + q] =
                    make_float4(f0.x * 0x1p-14f, f0.y * 0x1p-14f,
                                f1.x * 0x1p-14f, f1.y * 0x1p-14f);
            }
        }
    }
}

extern "C" void kernel_launch(void* const* d_in, const int* in_sizes, int n_in,
                              void* d_out, int out_size)
{
    const float* coords = (const float*)d_in[0];
    const float* ts     = (const float*)d_in[1];
    const float* tables = (const float*)d_in[2];
    float* out          = (float*)d_out;

    int n = in_sizes[0] / 3;

    ResArr ra;
    for (int l = 0; l < N_LEVELS; ++l) {
        double f = (double)l / 15.0;
        double v = exp(log(16.0) * (1.0 - f) + log(512.0) * f);
        ra.r[l] = (int)v;
    }

    const int smem_main = HASHMAP_SIZE * (int)sizeof(__half2);        // 131072
    const int smem_tp   = TP_PTS * TP_STRIDE * (int)sizeof(__half2);  // 69632
    static int configured = 0;
    if (!configured) {
        cudaFuncSetAttribute(hash_enc4d_smem_kernel,
                             cudaFuncAttributeMaxDynamicSharedMemorySize, smem_main);
        cudaFuncSetAttribute(transpose_kernel,
                             cudaFuncAttributeMaxDynamicSharedMemorySize, smem_tp);
        configured = 1;
    }

    // 1) 4-wave level-fastest encode (4 pts/thread, vectorized coords inline)
    dim3 grid(N_LEVELS, (n + PTS_PER_CTA - 1) / PTS_PER_CTA);
    hash_enc4d_smem_kernel<<<grid, CTA_THREADS, smem_main>>>(coords, ts, tables, ra, n);

    // 2) full-occupancy conflict-free transpose + descale
    int tp_blocks = (n + TP_PTS - 1) / TP_PTS;
    transpose_kernel<<<tp_blocks, TP_THREADS, smem_tp>>>(out, n);
}